// round 8
// baseline (speedup 1.0000x reference)
#include <cuda_runtime.h>
#include <cuda_bf16.h>
#include <cstdint>

// LengthRegulator fused single-kernel:
//   x (32,512,384) f32, duration (32,512) int64/int32 (runtime-detected), max_len=4096
//   out = (32,4096,384) f32 gather-expand + mel_len tail (layout inferred from out_size).
//
// Each block handles 16 consecutive output rows of one batch. It redundantly
// recomputes the batch cumsum from the (L2-resident) duration vector, binary-
// searches its 16 positions (10 steps — log2(512)+1), then does the
// bandwidth-bound gather/store.

#define B_   32
#define T_   512
#define C_   384
#define ML_  4096
#define C4_  (C_ / 4)            // 96 float4 per row
#define RPB  16                  // rows per block
#define UNR  4                   // rows per thread (RPB / blockDim.y)
#define BPB  (ML_ / RPB)         // 256 blocks per batch
#define NTHR (C4_ * 4)           // 384 threads

__global__ void __launch_bounds__(NTHR) lr_fused_kernel(const float4* __restrict__ x,
                                                        const void* __restrict__ dur_raw,
                                                        float* __restrict__ out,
                                                        int mel_mode) {
    __shared__ int s_csum[T_];
    __shared__ int s_wsum[16];

    const int c4   = threadIdx.x;              // 0..95
    const int ty   = threadIdx.y;              // 0..3
    const int tid  = ty * C4_ + c4;            // 0..383 (hardware-linear)
    const int lane = tid & 31;
    const int wid  = tid >> 5;                 // 0..11

    const int b   = blockIdx.x >> 8;           // blockIdx.x / BPB
    const int bib = blockIdx.x & (BPB - 1);    // block within batch

    // ---- int64 vs int32 detection: odd int32 words of first 512 elements ----
    int pred = 0;
    #pragma unroll
    for (int i = tid; i < T_; i += NTHR)
        pred |= ((const int*)dur_raw)[2 * i + 1];
    const int is32 = __syncthreads_or(pred != 0);

    // ---- load clamped durations for this batch ----
    #pragma unroll
    for (int i = tid; i < T_; i += NTHR) {
        long long dv;
        if (is32) dv = (long long)((const int*)dur_raw)[(size_t)b * T_ + i];
        else      dv = ((const long long*)dur_raw)[(size_t)b * T_ + i];
        s_csum[i] = dv > 0 ? (int)dv : 0;
    }
    __syncthreads();

    // ---- inclusive scan: 16 chunks of 32, warps 0..11 sweep chunks ----
    for (int chunk = wid; chunk < 16; chunk += 12) {
        int v = s_csum[chunk * 32 + lane];
        #pragma unroll
        for (int off = 1; off < 32; off <<= 1) {
            int n = __shfl_up_sync(0xffffffffu, v, off);
            if (lane >= off) v += n;
        }
        s_csum[chunk * 32 + lane] = v;
        if (lane == 31) s_wsum[chunk] = v;
    }
    __syncthreads();

    if (wid == 0) {                           // scan the 16 chunk totals
        int wv = (lane < 16) ? s_wsum[lane] : 0;
        #pragma unroll
        for (int off = 1; off < 16; off <<= 1) {
            int n = __shfl_up_sync(0xffffffffu, wv, off);
            if (lane >= off) wv += n;
        }
        if (lane < 16) s_wsum[lane] = wv;
    }
    __syncthreads();

    #pragma unroll
    for (int i = tid; i < T_; i += NTHR)
        if (i >= 32) s_csum[i] += s_wsum[(i >> 5) - 1];
    __syncthreads();

    const int mel = s_csum[T_ - 1];

    // ---- mel_len tail (first block of each batch) ----
    if (bib == 0 && tid == 0) {
        const size_t total = (size_t)B_ * ML_ * C_;
        if (mel_mode == 1)      out[total + b] = (float)mel;
        else if (mel_mode == 2) ((long long*)(out + total))[b] = (long long)mel;
    }

    // ---- searchsorted(csum, p, side='right'), 4 interleaved queries ----
    int p[UNR], lo[UNR], hi[UNR];
    #pragma unroll
    for (int k = 0; k < UNR; ++k) {
        p[k]  = bib * RPB + ty + 4 * k;
        lo[k] = 0;
        hi[k] = T_;
    }
    #pragma unroll
    for (int it = 0; it < 10; ++it) {          // 512 -> size 1 needs 9, +1 to resolve
        #pragma unroll
        for (int k = 0; k < UNR; ++k) {
            if (lo[k] < hi[k]) {
                int mid = (lo[k] + hi[k]) >> 1;
                if (s_csum[mid] <= p[k]) lo[k] = mid + 1; else hi[k] = mid;
            }
        }
    }

    int idx[UNR];
    #pragma unroll
    for (int k = 0; k < UNR; ++k)
        idx[k] = (p[k] >= mel) ? -1 : (lo[k] < T_ - 1 ? lo[k] : T_ - 1);

    // ---- bandwidth-bound gather + streaming store ----
    const float4* xb = x + (size_t)b * T_ * C4_;
    float4 v[UNR];
    #pragma unroll
    for (int k = 0; k < UNR; ++k) {
        if (idx[k] >= 0) v[k] = __ldg(&xb[(size_t)idx[k] * C4_ + c4]);
        else             v[k] = make_float4(0.f, 0.f, 0.f, 0.f);
    }

    float4* out4 = (float4*)out;
    const size_t rowBase = (size_t)blockIdx.x * RPB + ty;
    #pragma unroll
    for (int k = 0; k < UNR; ++k)
        __stcs(&out4[(rowBase + 4 * k) * C4_ + c4], v[k]);   // evict-first: keep x in L2
}

// ---------------------------------------------------------------------------
extern "C" void kernel_launch(void* const* d_in, const int* in_sizes, int n_in,
                              void* d_out, int out_size) {
    const float* x   = (const float*)d_in[0];
    const void*  dur = d_in[1];
    float* out = (float*)d_out;

    const long long total = (long long)B_ * ML_ * C_;
    const long long extra = (long long)out_size - total;
    int mel_mode = 0;
    if (extra == B_)          mel_mode = 1;   // float32 tail
    else if (extra == 2 * B_) mel_mode = 2;   // raw int64 tail

    dim3 blk(C4_, 4);
    lr_fused_kernel<<<(B_ * ML_) / RPB, blk>>>((const float4*)x, dur, out, mel_mode);
}

// round 9
// speedup vs baseline: 1.5447x; 1.5447x over previous
#include <cuda_runtime.h>
#include <cuda_bf16.h>
#include <cstdint>

// LengthRegulator, single launch with in-grid producer->consumer sync:
//   x (32,512,384) f32, duration (32,512) int64/int32 (runtime-detected), max_len=4096
//   out = (32,4096,384) f32 gather-expand + mel_len tail (layout inferred from out_size).
//
// Blocks 0..31 (guaranteed resident in wave 1) each scan one batch's durations,
// searchsorted all 4096 positions, and publish g_idx. Every block then waits on
// a completion counter and runs the bandwidth-bound expand body (identical to
// the proven two-kernel expand: ~6 TB/s effective, issue ~18%).

#define B_   32
#define T_   512
#define C_   384
#define ML_  4096
#define C4_  (C_ / 4)            // 96 float4 per row
#define RPB  16                  // rows per expand block
#define UNR  4                   // rows per thread
#define NTHR (C4_ * 4)           // 384 threads
#define GRID ((B_ * ML_) / RPB)  // 8192 blocks

__device__ int g_idx[B_ * ML_];          // input-row index per output row; -1 = masked
__device__ int g_ready;                  // producer completion counter (self-resetting)
__device__ unsigned int g_done;          // block completion counter (self-resetting)

__global__ void __launch_bounds__(NTHR) lr_fused_kernel(const float4* __restrict__ x,
                                                        const void* __restrict__ dur_raw,
                                                        float* __restrict__ out,
                                                        int mel_mode) {
    const int c4  = threadIdx.x;             // 0..95
    const int ty  = threadIdx.y;             // 0..3
    const int tid = ty * C4_ + c4;           // 0..383

    // ================= PRODUCER: blocks 0..31 build g_idx for batch=blockIdx =================
    if (blockIdx.x < B_) {
        __shared__ int s_csum[T_];
        __shared__ int s_wsum[16];
        const int b    = blockIdx.x;
        const int lane = tid & 31;
        const int wid  = tid >> 5;           // 0..11

        // int64 vs int32: odd int32 words of first 512 elements all zero => int64
        int pred = 0;
        for (int i = tid; i < T_; i += NTHR)
            pred |= ((const int*)dur_raw)[2 * i + 1];
        const int is32 = __syncthreads_or(pred != 0);

        for (int i = tid; i < T_; i += NTHR) {
            long long dv;
            if (is32) dv = (long long)((const int*)dur_raw)[(size_t)b * T_ + i];
            else      dv = ((const long long*)dur_raw)[(size_t)b * T_ + i];
            s_csum[i] = dv > 0 ? (int)dv : 0;
        }
        __syncthreads();

        // inclusive scan: 16 chunks of 32, warps 0..11 sweep chunks
        for (int chunk = wid; chunk < 16; chunk += 12) {
            int v = s_csum[chunk * 32 + lane];
            #pragma unroll
            for (int off = 1; off < 32; off <<= 1) {
                int n = __shfl_up_sync(0xffffffffu, v, off);
                if (lane >= off) v += n;
            }
            s_csum[chunk * 32 + lane] = v;
            if (lane == 31) s_wsum[chunk] = v;
        }
        __syncthreads();
        if (wid == 0) {
            int wv = (lane < 16) ? s_wsum[lane] : 0;
            #pragma unroll
            for (int off = 1; off < 16; off <<= 1) {
                int n = __shfl_up_sync(0xffffffffu, wv, off);
                if (lane >= off) wv += n;
            }
            if (lane < 16) s_wsum[lane] = wv;
        }
        __syncthreads();
        for (int i = tid; i < T_; i += NTHR)
            if (i >= 32) s_csum[i] += s_wsum[(i >> 5) - 1];
        __syncthreads();

        const int mel = s_csum[T_ - 1];

        if (tid == 0) {
            const size_t total = (size_t)B_ * ML_ * C_;
            if (mel_mode == 1)      out[total + b] = (float)mel;
            else if (mel_mode == 2) ((long long*)(out + total))[b] = (long long)mel;
        }

        // searchsorted(csum, p, 'right') for all 4096 positions, branchless 9-step
        for (int p = tid; p < ML_; p += NTHR) {
            int r;
            if (p >= mel) {
                r = -1;
            } else {
                int pos = 0;
                #pragma unroll
                for (int s = 256; s > 0; s >>= 1)
                    if (s_csum[pos + s - 1] <= p) pos += s;
                r = pos < (T_ - 1) ? pos : (T_ - 1);   // cap (p<mel keeps this exact)
            }
            g_idx[b * ML_ + p] = r;
        }

        __threadfence();                      // publish g_idx before signaling
        __syncthreads();
        if (tid == 0) atomicAdd(&g_ready, 1);
    }

    // ================= WAIT: all blocks until all 32 producers signaled =================
    if (tid == 0) {
        volatile int* r = &g_ready;
        while (*r < B_) { }
        __threadfence();                      // acquire before consuming g_idx
    }
    __syncthreads();

    // ================= EXPAND: identical to proven two-kernel body =================
    const int rowBase = blockIdx.x * RPB + ty;          // rows: rowBase + 4*k
    const int b       = (blockIdx.x * RPB) >> 12;       // batch (RPB divides ML_)

    int idx[UNR];
    #pragma unroll
    for (int k = 0; k < UNR; ++k)
        idx[k] = __ldcg(&g_idx[rowBase + 4 * k]);       // warp-uniform, L2 read

    const float4* xb = x + (size_t)b * T_ * C4_;
    float4 v[UNR];
    #pragma unroll
    for (int k = 0; k < UNR; ++k) {
        if (idx[k] >= 0) v[k] = __ldg(&xb[(size_t)idx[k] * C4_ + c4]);
        else             v[k] = make_float4(0.f, 0.f, 0.f, 0.f);
    }

    float4* out4 = (float4*)out;
    #pragma unroll
    for (int k = 0; k < UNR; ++k)
        __stcs(&out4[(size_t)(rowBase + 4 * k) * C4_ + c4], v[k]);  // evict-first

    // ================= RESET flags (last block) for deterministic graph replay =================
    __syncthreads();
    if (tid == 0) {
        if (atomicAdd(&g_done, 1u) == (unsigned)(GRID - 1)) {
            g_done  = 0u;
            g_ready = 0;
        }
    }
}

// ---------------------------------------------------------------------------
extern "C" void kernel_launch(void* const* d_in, const int* in_sizes, int n_in,
                              void* d_out, int out_size) {
    const float* x   = (const float*)d_in[0];
    const void*  dur = d_in[1];
    float* out = (float*)d_out;

    const long long total = (long long)B_ * ML_ * C_;
    const long long extra = (long long)out_size - total;
    int mel_mode = 0;
    if (extra == B_)          mel_mode = 1;   // float32 tail
    else if (extra == 2 * B_) mel_mode = 2;   // raw int64 tail

    dim3 blk(C4_, 4);
    lr_fused_kernel<<<GRID, blk>>>((const float4*)x, dur, out, mel_mode);
}

// round 10
// speedup vs baseline: 1.5873x; 1.0276x over previous
#include <cuda_runtime.h>
#include <cuda_bf16.h>
#include <cstdint>

// LengthRegulator, single launch, in-grid producer->consumer sync:
//   x (32,512,384) f32, duration (32,512) int64/int32 (runtime-detected), max_len=4096
//   out = (32,4096,384) f32 gather-expand + mel_len tail (layout inferred from out_size).
//
// Producers (blocks 0..31, guaranteed resident in wave 1): scan one batch's
// durations, then INVERSE-SCATTER the index map (thread i writes idx=i into
// g_idx[csum[i-1]..csum[i])) — no binary search, ~1us critical path.
// All blocks then wait on a 32-count flag and run the bandwidth-bound expand
// (already at ~95% of the LTS-cap floor).

#define B_   32
#define T_   512
#define C_   384
#define ML_  4096
#define C4_  (C_ / 4)            // 96 float4 per row
#define RPB  16                  // rows per expand block
#define UNR  4                   // rows per thread
#define NTHR (C4_ * 4)           // 384 threads
#define GRID ((B_ * ML_) / RPB)  // 8192 blocks

__device__ int g_idx[B_ * ML_];          // input-row index per output row; -1 = masked
__device__ int g_ready;                  // producer completion counter (self-resetting)
__device__ unsigned int g_done;          // block completion counter (self-resetting)

__global__ void __launch_bounds__(NTHR) lr_fused_kernel(const float4* __restrict__ x,
                                                        const void* __restrict__ dur_raw,
                                                        float* __restrict__ out,
                                                        int mel_mode) {
    const int c4  = threadIdx.x;             // 0..95
    const int ty  = threadIdx.y;             // 0..3
    const int tid = ty * C4_ + c4;           // 0..383

    // ================= PRODUCER: blocks 0..31, one batch each =================
    if (blockIdx.x < B_) {
        __shared__ int s_csum[T_];
        __shared__ int s_wsum[16];
        const int b    = blockIdx.x;
        const int lane = tid & 31;
        const int wid  = tid >> 5;           // 0..11

        // int64 vs int32: odd int32 words of first 512 elements all zero => int64
        int pred = 0;
        for (int i = tid; i < T_; i += NTHR)
            pred |= ((const int*)dur_raw)[2 * i + 1];
        const int is32 = __syncthreads_or(pred != 0);

        for (int i = tid; i < T_; i += NTHR) {
            long long dv;
            if (is32) dv = (long long)((const int*)dur_raw)[(size_t)b * T_ + i];
            else      dv = ((const long long*)dur_raw)[(size_t)b * T_ + i];
            s_csum[i] = dv > 0 ? (int)dv : 0;
        }
        __syncthreads();

        // inclusive scan: 16 chunks of 32, warps 0..11 sweep chunks
        for (int chunk = wid; chunk < 16; chunk += 12) {
            int v = s_csum[chunk * 32 + lane];
            #pragma unroll
            for (int off = 1; off < 32; off <<= 1) {
                int n = __shfl_up_sync(0xffffffffu, v, off);
                if (lane >= off) v += n;
            }
            s_csum[chunk * 32 + lane] = v;
            if (lane == 31) s_wsum[chunk] = v;
        }
        __syncthreads();
        if (wid == 0) {
            int wv = (lane < 16) ? s_wsum[lane] : 0;
            #pragma unroll
            for (int off = 1; off < 16; off <<= 1) {
                int n = __shfl_up_sync(0xffffffffu, wv, off);
                if (lane >= off) wv += n;
            }
            if (lane < 16) s_wsum[lane] = wv;
        }
        __syncthreads();
        for (int i = tid; i < T_; i += NTHR)
            if (i >= 32) s_csum[i] += s_wsum[(i >> 5) - 1];
        __syncthreads();

        const int mel = s_csum[T_ - 1];

        if (tid == 0) {
            const size_t total = (size_t)B_ * ML_ * C_;
            if (mel_mode == 1)      out[total + b] = (float)mel;
            else if (mel_mode == 2) ((long long*)(out + total))[b] = (long long)mel;
        }

        // INVERSE SCATTER: thread i fills g_idx[csum[i-1] .. csum[i]) = i
        // (searchsorted 'right' inverse; exact for p < mel, clip never binds since i <= T-1)
        int* gb = g_idx + b * ML_;
        for (int i = tid; i < T_; i += NTHR) {
            int start = (i == 0) ? 0 : s_csum[i - 1];
            int end   = s_csum[i];
            if (end > ML_) end = ML_;
            for (int p = start; p < end; ++p) gb[p] = i;
        }
        // masked tail
        for (int p = mel + tid; p < ML_; p += NTHR) gb[p] = -1;

        __threadfence();                      // publish g_idx before signaling
        __syncthreads();
        if (tid == 0) atomicAdd(&g_ready, 1);
    }

    // ================= WAIT: until all 32 producers signaled =================
    if (tid == 0) {
        volatile int* r = &g_ready;
        while (*r < B_) { }
        __threadfence();                      // acquire before consuming g_idx
    }
    __syncthreads();

    // ================= EXPAND: proven bandwidth-bound body =================
    const int rowBase = blockIdx.x * RPB + ty;          // rows: rowBase + 4*k
    const int b       = (blockIdx.x * RPB) >> 12;       // batch (RPB divides ML_)

    int idx[UNR];
    #pragma unroll
    for (int k = 0; k < UNR; ++k)
        idx[k] = g_idx[rowBase + 4 * k];                // warp-uniform

    const float4* xb = x + (size_t)b * T_ * C4_;
    float4 v[UNR];
    #pragma unroll
    for (int k = 0; k < UNR; ++k) {
        if (idx[k] >= 0) v[k] = __ldg(&xb[(size_t)idx[k] * C4_ + c4]);
        else             v[k] = make_float4(0.f, 0.f, 0.f, 0.f);
    }

    float4* out4 = (float4*)out;
    #pragma unroll
    for (int k = 0; k < UNR; ++k)
        __stcs(&out4[(size_t)(rowBase + 4 * k) * C4_ + c4], v[k]);  // evict-first

    // ================= RESET flags (last block) for deterministic replay =================
    __syncthreads();
    if (tid == 0) {
        if (atomicAdd(&g_done, 1u) == (unsigned)(GRID - 1)) {
            g_done  = 0u;
            g_ready = 0;
        }
    }
}

// ---------------------------------------------------------------------------
extern "C" void kernel_launch(void* const* d_in, const int* in_sizes, int n_in,
                              void* d_out, int out_size) {
    const float* x   = (const float*)d_in[0];
    const void*  dur = d_in[1];
    float* out = (float*)d_out;

    const long long total = (long long)B_ * ML_ * C_;
    const long long extra = (long long)out_size - total;
    int mel_mode = 0;
    if (extra == B_)          mel_mode = 1;   // float32 tail
    else if (extra == 2 * B_) mel_mode = 2;   // raw int64 tail

    dim3 blk(C4_, 4);
    lr_fused_kernel<<<GRID, blk>>>((const float4*)x, dur, out, mel_mode);
}